// round 2
// baseline (speedup 1.0000x reference)
#include <cuda_runtime.h>
#include <math.h>

// Problem shape (fixed for this instance)
#define Bv 4
#define Hv 256
#define Wv 256
#define CH 32
#define NPIX (Bv*Hv*Wv)          // 262144
#define KK 81
#define NB 10

// Tile config
#define TBX 32
#define TBY 8
#define HALO 4
#define TW (TBX + 2*HALO)        // 40
#define TH (TBY + 2*HALO)        // 16
#define PLANE (TW*TH)            // 640
#define PL (PLANE + 1)           // 641 (pad: conflict-free transposing writes)

// Scratch (static device globals; runtime allocation is forbidden)
__device__ float    g_w[(size_t)NPIX * CH];
__device__ float    g_mapped[(size_t)NPIX * CH];
__device__ float    g_fg[(size_t)NPIX * CH];
__device__ unsigned g_smask[6 * NPIX];   // planes 0..2: pos bits, 3..5: zero bits
__device__ float    g_y[KK], g_vp[KK], g_wm[KK];
__device__ float    g_scal[2];   // [0]=reg_weight, [1]=step_length

// ---------------------------------------------------------------------------
// Setup: per-k constants from the soft-binned distance map + scalars
// ---------------------------------------------------------------------------
__global__ void setup_consts(const float* __restrict__ tw,
                             const float* __restrict__ sw,
                             const float* __restrict__ mw,
                             const float* __restrict__ wreg,
                             const float* __restrict__ lstep) {
    int k = threadIdx.x;
    if (k < KK) {
        int i = k / 9, j = k % 9;
        float di = (float)(i - 4), dj = (float)(j - 4);
        float dist = sqrtf(di * di + dj * dj);
        float y = 0.f, vp = 0.f, m = 0.f;
        #pragma unroll
        for (int b = 0; b < NB; b++) {
            float t = dist * 2.0f - (float)b;   // dist / BIN_DISP - b
            float bv;
            if (i < 8) bv = fmaxf(0.f, 1.f - fabsf(t));          // rows 0..7
            else       bv = fminf(fmaxf(1.f + t, 0.f), 1.f);     // row 8 (clip quirk)
            y  += bv * tw[b];
            vp += bv * sw[b];
            m  += bv * mw[b];
        }
        g_y[k]  = y;
        g_vp[k] = vp;
        g_wm[k] = 1.f / (1.f + expf(-m));
    } else if (k == KK) {
        float r  = wreg[0] * wreg[0];
        float lo = (1e-5f * 1e-5f) / ((float)CH * (float)CH);
        g_scal[0] = fmaxf(r, lo);
        g_scal[1] = expf(lstep[0]);
    }
}

// ---------------------------------------------------------------------------
// w0 = beta * ref / (mean(ref^2) + 1e-6)
// ---------------------------------------------------------------------------
__global__ void init_w(const float* __restrict__ ref, const float* __restrict__ beta) {
    int p = blockIdx.x * blockDim.x + threadIdx.x;
    if (p >= NPIX) return;
    const float4* rp = (const float4*)(ref + (size_t)p * CH);
    float4 v[8];
    float ss = 0.f;
    #pragma unroll
    for (int i = 0; i < 8; i++) {
        v[i] = rp[i];
        ss += v[i].x * v[i].x + v[i].y * v[i].y + v[i].z * v[i].z + v[i].w * v[i].w;
    }
    float sc = beta[0] / (ss * (1.f / (float)CH) + 1e-6f);
    float4* wp = (float4*)(g_w + (size_t)p * CH);
    #pragma unroll
    for (int i = 0; i < 8; i++) {
        v[i].x *= sc; v[i].y *= sc; v[i].z *= sc; v[i].w *= sc;
        wp[i] = v[i];
    }
}

// ---------------------------------------------------------------------------
// Halo tile loader: ref[b, y0-4 .. y0+TBY+3, x0-4 .. x0+TBX+3, :]
// channel-major smem planes (Rs[c*PL + pix]), zero padding outside image.
// ---------------------------------------------------------------------------
__device__ __forceinline__ void load_ref_tile(float* Rs, const float* __restrict__ ref,
                                              int b, int y0, int x0) {
    int tid = threadIdx.x;
    #pragma unroll
    for (int i = 0; i < (PLANE * CH) / 256; i++) {   // 80 iters
        int e = tid + i * 256;
        int pix = e >> 5, c = e & 31;
        int py = pix / TW, px = pix - py * TW;
        int gy = y0 - HALO + py, gx = x0 - HALO + px;
        float v = 0.f;
        if ((unsigned)gy < (unsigned)Hv && (unsigned)gx < (unsigned)Wv)
            v = ref[(((size_t)(b * Hv + gy) * Wv) + gx) * CH + c];
        Rs[c * PL + pix] = v;
    }
}

extern __shared__ float sdyn[];

// ---------------------------------------------------------------------------
// Step A: c = LCV(w, ref); mapped = (dact * (act - vp*y)) @ mr_w + mr_b
//         store 2-bit sign state of c (for dact reconstruction in step C)
// ---------------------------------------------------------------------------
__global__ void __launch_bounds__(256)
k_stepA(const float* __restrict__ ref,
        const float* __restrict__ mr_w, const float* __restrict__ mr_b) {
    float* Rs = sdyn;
    float* M  = sdyn + CH * PL;
    float* ky = M + KK * CH;
    float* kv = ky + KK;
    float* ka = kv + KK;

    int b = blockIdx.z, y0 = blockIdx.y * TBY, x0 = blockIdx.x * TBX;
    load_ref_tile(Rs, ref, b, y0, x0);
    for (int e = threadIdx.x; e < KK * CH; e += 256) M[e] = __ldg(mr_w + e);
    if (threadIdx.x < KK) {
        ky[threadIdx.x] = g_y[threadIdx.x];
        kv[threadIdx.x] = g_vp[threadIdx.x];
        ka[threadIdx.x] = g_wm[threadIdx.x];
    }
    __syncthreads();

    int txl = threadIdx.x & 31, tyl = threadIdx.x >> 5;
    int p = (b * Hv + (y0 + tyl)) * Wv + (x0 + txl);

    float wv[CH];
    {
        const float4* w4 = (const float4*)(g_w + (size_t)p * CH);
        #pragma unroll
        for (int i = 0; i < 8; i++) {
            float4 t = w4[i];
            wv[4*i] = t.x; wv[4*i+1] = t.y; wv[4*i+2] = t.z; wv[4*i+3] = t.w;
        }
    }
    float macc[CH];
    #pragma unroll
    for (int c = 0; c < CH; c++) macc[c] = __ldg(mr_b + c);

    unsigned s0 = 0, s1 = 0, s2 = 0;   // pos bits (c > 0)
    unsigned z0 = 0, z1 = 0, z2 = 0;   // zero bits (c == 0)
    int cen = (tyl + HALO) * TW + (txl + HALO);
    int k = 0;
    for (int di = -HALO; di <= HALO; di++) {
        for (int dj = -HALO; dj <= HALO; dj++, k++) {
            const float* rp = Rs + cen + di * TW + dj;
            float acc = 0.f;
            #pragma unroll
            for (int c = 0; c < CH; c++) acc = fmaf(wv[c], rp[c * PL], acc);
            float cm = acc * (1.f / (float)CH);
            float a = ka[k], vp = kv[k], yk = ky[k];
            // 3-state sign semantics (jnp.sign): -1 / 0 / +1
            float sgn = (cm > 0.f) ? 1.f : ((cm < 0.f) ? -1.f : 0.f);
            float half1ma = 0.5f * (1.f - a), half1pa = 0.5f * (1.f + a);
            float dact = vp * (half1ma * sgn + half1pa);
            float act  = vp * (half1ma * fabsf(cm) + half1pa * cm);
            float sv = dact * (act - vp * yk);
            unsigned pbit = (cm > 0.f)  ? 1u : 0u;
            unsigned zbit = (cm == 0.f) ? 1u : 0u;
            unsigned sh = (unsigned)k & 31u;
            if (k < 32)      { s0 |= pbit << sh; z0 |= zbit << sh; }
            else if (k < 64) { s1 |= pbit << sh; z1 |= zbit << sh; }
            else             { s2 |= pbit << sh; z2 |= zbit << sh; }
            const float* m = M + k * CH;
            #pragma unroll
            for (int c = 0; c < CH; c++) macc[c] = fmaf(sv, m[c], macc[c]);
        }
    }

    float4* op = (float4*)(g_mapped + (size_t)p * CH);
    #pragma unroll
    for (int i = 0; i < 8; i++) {
        float4 t;
        t.x = macc[4*i]; t.y = macc[4*i+1]; t.z = macc[4*i+2]; t.w = macc[4*i+3];
        op[i] = t;
    }
    g_smask[p]            = s0;
    g_smask[NPIX + p]     = s1;
    g_smask[2 * NPIX + p] = s2;
    g_smask[3 * NPIX + p] = z0;
    g_smask[4 * NPIX + p] = z1;
    g_smask[5 * NPIX + p] = z2;
}

// ---------------------------------------------------------------------------
// Step B: fg = reg_weight * w + LCV(mapped, ref) @ lr_w + lr_b
// ---------------------------------------------------------------------------
__global__ void __launch_bounds__(256)
k_stepB(const float* __restrict__ ref,
        const float* __restrict__ lr_w, const float* __restrict__ lr_b) {
    float* Rs = sdyn;
    float* M  = sdyn + CH * PL;

    int b = blockIdx.z, y0 = blockIdx.y * TBY, x0 = blockIdx.x * TBX;
    load_ref_tile(Rs, ref, b, y0, x0);
    for (int e = threadIdx.x; e < KK * CH; e += 256) M[e] = __ldg(lr_w + e);
    __syncthreads();

    int txl = threadIdx.x & 31, tyl = threadIdx.x >> 5;
    int p = (b * Hv + (y0 + tyl)) * Wv + (x0 + txl);

    float wv[CH];
    {
        const float4* m4 = (const float4*)(g_mapped + (size_t)p * CH);
        #pragma unroll
        for (int i = 0; i < 8; i++) {
            float4 t = m4[i];
            wv[4*i] = t.x; wv[4*i+1] = t.y; wv[4*i+2] = t.z; wv[4*i+3] = t.w;
        }
    }
    float macc[CH];
    #pragma unroll
    for (int c = 0; c < CH; c++) macc[c] = __ldg(lr_b + c);

    int cen = (tyl + HALO) * TW + (txl + HALO);
    int k = 0;
    for (int di = -HALO; di <= HALO; di++) {
        for (int dj = -HALO; dj <= HALO; dj++, k++) {
            const float* rp = Rs + cen + di * TW + dj;
            float acc = 0.f;
            #pragma unroll
            for (int c = 0; c < CH; c++) acc = fmaf(wv[c], rp[c * PL], acc);
            float cm = acc * (1.f / (float)CH);
            const float* m = M + k * CH;
            #pragma unroll
            for (int c = 0; c < CH; c++) macc[c] = fmaf(cm, m[c], macc[c]);
        }
    }

    float reg = g_scal[0];
    const float4* w4 = (const float4*)(g_w + (size_t)p * CH);
    float4* fp = (float4*)(g_fg + (size_t)p * CH);
    #pragma unroll
    for (int i = 0; i < 8; i++) {
        float4 wt = w4[i];
        float4 t;
        t.x = reg * wt.x + macc[4*i];
        t.y = reg * wt.y + macc[4*i+1];
        t.z = reg * wt.z + macc[4*i+2];
        t.w = reg * wt.w + macc[4*i+3];
        fp[i] = t;
    }
}

// ---------------------------------------------------------------------------
// Step C: scores = dact * LCV(fg, ref); alpha = sum(fg^2)/sum(scores^2)
//         w_out = w + alpha * step * fg
// ---------------------------------------------------------------------------
__global__ void __launch_bounds__(256)
k_stepC(const float* __restrict__ ref, float* __restrict__ dout, int last) {
    float* Rs = sdyn;
    float* kv = sdyn + CH * PL;
    float* ka = kv + KK;

    int b = blockIdx.z, y0 = blockIdx.y * TBY, x0 = blockIdx.x * TBX;
    load_ref_tile(Rs, ref, b, y0, x0);
    if (threadIdx.x < KK) {
        kv[threadIdx.x] = g_vp[threadIdx.x];
        ka[threadIdx.x] = g_wm[threadIdx.x];
    }
    __syncthreads();

    int txl = threadIdx.x & 31, tyl = threadIdx.x >> 5;
    int p = (b * Hv + (y0 + tyl)) * Wv + (x0 + txl);

    float fv[CH];
    float num = 0.f;
    {
        const float4* f4 = (const float4*)(g_fg + (size_t)p * CH);
        #pragma unroll
        for (int i = 0; i < 8; i++) {
            float4 t = f4[i];
            fv[4*i] = t.x; fv[4*i+1] = t.y; fv[4*i+2] = t.z; fv[4*i+3] = t.w;
            num += t.x * t.x + t.y * t.y + t.z * t.z + t.w * t.w;
        }
    }
    unsigned s0 = g_smask[p];
    unsigned s1 = g_smask[NPIX + p];
    unsigned s2 = g_smask[2 * NPIX + p];
    unsigned z0 = g_smask[3 * NPIX + p];
    unsigned z1 = g_smask[4 * NPIX + p];
    unsigned z2 = g_smask[5 * NPIX + p];

    float den = 0.f;
    int cen = (tyl + HALO) * TW + (txl + HALO);
    int k = 0;
    for (int di = -HALO; di <= HALO; di++) {
        for (int dj = -HALO; dj <= HALO; dj++, k++) {
            const float* rp = Rs + cen + di * TW + dj;
            float acc = 0.f;
            #pragma unroll
            for (int c = 0; c < CH; c++) acc = fmaf(fv[c], rp[c * PL], acc);
            float cm = acc * (1.f / (float)CH);
            unsigned sh = (unsigned)k & 31u;
            unsigned pbit, zbit;
            if (k < 32)      { pbit = (s0 >> sh) & 1u; zbit = (z0 >> sh) & 1u; }
            else if (k < 64) { pbit = (s1 >> sh) & 1u; zbit = (z1 >> sh) & 1u; }
            else             { pbit = (s2 >> sh) & 1u; zbit = (z2 >> sh) & 1u; }
            float sgn = pbit ? 1.f : (zbit ? 0.f : -1.f);
            float a = ka[k];
            float dact = kv[k] * (0.5f * (1.f - a) * sgn + 0.5f * (1.f + a));
            float sc = dact * cm;
            den += sc * sc;
        }
    }

    float alpha = (num / den) * g_scal[1];
    float* outp = last ? dout : g_w;
    const float4* w4 = (const float4*)(g_w + (size_t)p * CH);
    float4* op = (float4*)(outp + (size_t)p * CH);
    #pragma unroll
    for (int i = 0; i < 8; i++) {
        float4 wt = w4[i];
        float4 t;
        t.x = wt.x + alpha * fv[4*i];
        t.y = wt.y + alpha * fv[4*i+1];
        t.z = wt.z + alpha * fv[4*i+2];
        t.w = wt.w + alpha * fv[4*i+3];
        op[i] = t;
    }
}

// ---------------------------------------------------------------------------
// Launch
// ---------------------------------------------------------------------------
#define SMEM_A ((CH*PL + KK*CH + 3*KK) * (int)sizeof(float))   // 93388
#define SMEM_B ((CH*PL + KK*CH) * (int)sizeof(float))          // 92416
#define SMEM_C ((CH*PL + 2*KK) * (int)sizeof(float))           // 82696

extern "C" void kernel_launch(void* const* d_in, const int* in_sizes, int n_in,
                              void* d_out, int out_size) {
    const float* ref  = (const float*)d_in[0];
    // d_in[1] = query_feature (unused by the reference computation)
    const float* beta = (const float*)d_in[2];
    const float* tw   = (const float*)d_in[3];
    const float* sw   = (const float*)d_in[4];
    const float* mw   = (const float*)d_in[5];
    const float* mrw  = (const float*)d_in[6];
    const float* mrb  = (const float*)d_in[7];
    const float* lrw  = (const float*)d_in[8];
    const float* lrb  = (const float*)d_in[9];
    const float* wreg = (const float*)d_in[10];
    const float* lst  = (const float*)d_in[11];

    cudaFuncSetAttribute(k_stepA, cudaFuncAttributeMaxDynamicSharedMemorySize, SMEM_A);
    cudaFuncSetAttribute(k_stepB, cudaFuncAttributeMaxDynamicSharedMemorySize, SMEM_B);
    cudaFuncSetAttribute(k_stepC, cudaFuncAttributeMaxDynamicSharedMemorySize, SMEM_C);

    setup_consts<<<1, 128>>>(tw, sw, mw, wreg, lst);
    init_w<<<NPIX / 256, 256>>>(ref, beta);

    dim3 grid(Wv / TBX, Hv / TBY, Bv);
    for (int it = 0; it < 3; it++) {
        k_stepA<<<grid, 256, SMEM_A>>>(ref, mrw, mrb);
        k_stepB<<<grid, 256, SMEM_B>>>(ref, lrw, lrb);
        k_stepC<<<grid, 256, SMEM_C>>>(ref, (float*)d_out, it == 2 ? 1 : 0);
    }
}